// round 15
// baseline (speedup 1.0000x reference)
#include <cuda_runtime.h>
#include <cuda_bf16.h>
#include <cstdint>

#define BD 2
#define SD 2048
#define ED 512
#define NH 8     // heads
#define DD 64    // head dim
#define PD 34    // num pos ids
#define TQ 128   // queries per CTA
#define TK 128   // keys per tile
#define NTILE (SD/TK)

// scratch (allocation-free)
__device__ __nv_bfloat16 g_Qh[BD*NH*SD*DD];
__device__ __nv_bfloat16 g_Ql[BD*NH*SD*DD];
__device__ __nv_bfloat16 g_Kh[BD*NH*SD*DD];
__device__ __nv_bfloat16 g_Kl[BD*NH*SD*DD];
__device__ __nv_bfloat16 g_Vh[BD*NH*SD*DD];
__device__ __nv_bfloat16 g_Vl[BD*NH*SD*DD];
__device__ float g_AttO[BD*SD*ED];
__device__ unsigned char g_rid8[BD*SD*SD];
__device__ __nv_bfloat16 g_Xh[BD*SD*ED];      // pre-split gemm input
__device__ __nv_bfloat16 g_Xl[BD*SD*ED];
__device__ __nv_bfloat16 g_Wh[ED*ED];         // pre-split gemm weight
__device__ __nv_bfloat16 g_Wl[ED*ED];

// ---------------------------------------------------------------------------
// common helpers
// ---------------------------------------------------------------------------
__device__ __forceinline__ uint32_t smem_u32(const void* p) {
    uint32_t a;
    asm("{ .reg .u64 t; cvta.to.shared.u64 t, %1; cvt.u32.u64 %0, t; }"
        : "=r"(a) : "l"(p));
    return a;
}
__device__ __forceinline__ void ldsm4(uint32_t addr, uint32_t* r) {
    asm volatile("ldmatrix.sync.aligned.m8n8.x4.shared.b16 {%0,%1,%2,%3}, [%4];"
                 : "=r"(r[0]), "=r"(r[1]), "=r"(r[2]), "=r"(r[3]) : "r"(addr));
}
__device__ __forceinline__ void ldsm2(uint32_t addr, uint32_t& r0, uint32_t& r1) {
    asm volatile("ldmatrix.sync.aligned.m8n8.x2.shared.b16 {%0,%1}, [%2];"
                 : "=r"(r0), "=r"(r1) : "r"(addr));
}
__device__ __forceinline__ void ldsm2t(uint32_t addr, uint32_t& r0, uint32_t& r1) {
    asm volatile("ldmatrix.sync.aligned.m8n8.x2.trans.shared.b16 {%0,%1}, [%2];"
                 : "=r"(r0), "=r"(r1) : "r"(addr));
}
__device__ __forceinline__ void mma16816(float* c, const uint32_t* a,
                                         uint32_t b0, uint32_t b1) {
    asm volatile("mma.sync.aligned.m16n8k16.row.col.f32.bf16.bf16.f32 "
                 "{%0,%1,%2,%3}, {%4,%5,%6,%7}, {%8,%9}, {%0,%1,%2,%3};"
                 : "+f"(c[0]), "+f"(c[1]), "+f"(c[2]), "+f"(c[3])
                 : "r"(a[0]), "r"(a[1]), "r"(a[2]), "r"(a[3]), "r"(b0), "r"(b1));
}
__device__ __forceinline__ uint32_t pack2(__nv_bfloat16 a, __nv_bfloat16 b) {
    return (uint32_t)__bfloat16_as_ushort(a) | ((uint32_t)__bfloat16_as_ushort(b) << 16);
}
__device__ __forceinline__ void split2(float x0, float x1, uint32_t& hi, uint32_t& lo) {
    __nv_bfloat16 h0 = __float2bfloat16(x0), h1 = __float2bfloat16(x1);
    hi = pack2(h0, h1);
    lo = pack2(__float2bfloat16(x0 - __bfloat162float(h0)),
               __float2bfloat16(x1 - __bfloat162float(h1)));
}
__device__ __forceinline__ void cp16(uint32_t dst, const void* src) {
    asm volatile("cp.async.cg.shared.global [%0], [%1], 16;" :: "r"(dst), "l"(src));
}
#define CP_COMMIT() asm volatile("cp.async.commit_group;" ::: "memory")
#define CP_WAIT(n)  asm volatile("cp.async.wait_group %0;" :: "n"(n) : "memory")

// ---------------------------------------------------------------------------
// rid int32 -> u8 pack (once)
// ---------------------------------------------------------------------------
__global__ __launch_bounds__(256) void rid_pack(const int* __restrict__ rid,
                                                unsigned char* __restrict__ out)
{
    size_t i = (size_t)blockIdx.x * 256 + threadIdx.x;   // 16 elems per thread
    const int4* src = (const int4*)rid + i * 4;
    int4 a = src[0], b = src[1], c = src[2], d = src[3];
    uint4 r;
    r.x = (uint32_t)a.x | ((uint32_t)a.y << 8) | ((uint32_t)a.z << 16) | ((uint32_t)a.w << 24);
    r.y = (uint32_t)b.x | ((uint32_t)b.y << 8) | ((uint32_t)b.z << 16) | ((uint32_t)b.w << 24);
    r.z = (uint32_t)c.x | ((uint32_t)c.y << 8) | ((uint32_t)c.z << 16) | ((uint32_t)c.w << 24);
    r.w = (uint32_t)d.x | ((uint32_t)d.y << 8) | ((uint32_t)d.z << 16) | ((uint32_t)d.w << 24);
    *(uint4*)(out + i * 16) = r;
}

// ---------------------------------------------------------------------------
// fp32 -> split bf16 (hi, lo), row-major preserved
// ---------------------------------------------------------------------------
__global__ __launch_bounds__(256) void to_split(const float* __restrict__ in,
                                                __nv_bfloat16* __restrict__ oh,
                                                __nv_bfloat16* __restrict__ ol)
{
    size_t i = ((size_t)blockIdx.x * 256 + threadIdx.x) * 4;
    float4 v = *(const float4*)(in + i);
    uint32_t h0, l0, h1, l1;
    split2(v.x, v.y, h0, l0);
    split2(v.z, v.w, h1, l1);
    *(uint2*)(oh + i) = make_uint2(h0, h1);
    *(uint2*)(ol + i) = make_uint2(l0, l1);
}

// ---------------------------------------------------------------------------
// HMMA split-bf16 GEMM (pre-split operands, cp.async double buffer, occ 2)
// ---------------------------------------------------------------------------
#define GXH  0
#define GXL  18432
#define GWH  36864
#define GWL  46080
#define GBUF 55296
#define GSMEM 110592

__device__ __forceinline__ void gemm_issue(uint32_t sb, int buf, int kt,
                                           int bm, int bn, int tid,
                                           const char* Xh, const char* Xl,
                                           const char* Wh, const char* Wl)
{
    const uint32_t bo = (uint32_t)buf * GBUF;
    const int k0b = kt * 128;
    for (int i = tid; i < 1024; i += 256) {
        int r = i >> 3;
        uint32_t cc = (uint32_t)(i & 7) * 16;
        uint32_t off = (uint32_t)r * 144 + cc;
        size_t g = (size_t)(bm + r) * 1024 + k0b + cc;
        cp16(sb + GXH + bo + off, Xh + g);
        cp16(sb + GXL + bo + off, Xl + g);
    }
    for (int i = tid; i < 512; i += 256) {
        int r = i >> 3;
        uint32_t cc = (uint32_t)(i & 7) * 16;
        uint32_t off = (uint32_t)r * 144 + cc;
        size_t g = (size_t)(bn + r) * 1024 + k0b + cc;
        cp16(sb + GWH + bo + off, Wh + g);
        cp16(sb + GWL + bo + off, Wl + g);
    }
}

__global__ __launch_bounds__(256, 2) void gemm_mma(const __nv_bfloat16* __restrict__ Xh_,
                                                   const __nv_bfloat16* __restrict__ Xl_,
                                                   const __nv_bfloat16* __restrict__ Wh_,
                                                   const __nv_bfloat16* __restrict__ Wl_,
                                                   float* __restrict__ out,
                                                   __nv_bfloat16* __restrict__ oh,
                                                   __nv_bfloat16* __restrict__ ol,
                                                   int scatter)
{
    extern __shared__ char smp[];
    const uint32_t sb = smem_u32(smp);
    const int tid = threadIdx.x, w = tid >> 5, lane = tid & 31;
    const int bm = blockIdx.x * 128, bn = blockIdx.y * 64;
    const char* Xh = (const char*)Xh_;
    const char* Xl = (const char*)Xl_;
    const char* Wh = (const char*)Wh_;
    const char* Wl = (const char*)Wl_;
    const int l8 = lane & 7, j = lane >> 3, l16 = lane & 15;
    const uint32_t a_off = (uint32_t)((w*16 + ((j&1)<<3) + l8)*144 + ((j>>1)<<4));
    const uint32_t b_off = (uint32_t)(l8*144 + ((l16>>3)<<4));

    float c[8][4];
    #pragma unroll
    for (int n = 0; n < 8; n++) { c[n][0]=0.f; c[n][1]=0.f; c[n][2]=0.f; c[n][3]=0.f; }

    gemm_issue(sb, 0, 0, bm, bn, tid, Xh, Xl, Wh, Wl);
    CP_COMMIT();

    for (int kt = 0; kt < 8; kt++) {
        const int buf = kt & 1;
        if (kt + 1 < 8) {
            gemm_issue(sb, buf ^ 1, kt + 1, bm, bn, tid, Xh, Xl, Wh, Wl);
            CP_COMMIT();
            CP_WAIT(1);
        } else {
            CP_WAIT(0);
        }
        __syncthreads();
        const uint32_t bo = (uint32_t)buf * GBUF;

        #pragma unroll
        for (int ks = 0; ks < 4; ks++) {
            uint32_t ah[4], al[4];
            ldsm4(sb + GXH + bo + a_off + ks*32, ah);
            ldsm4(sb + GXL + bo + a_off + ks*32, al);
            #pragma unroll
            for (int n = 0; n < 8; n++) {
                uint32_t bh0, bh1, bl0, bl1;
                uint32_t boW = (uint32_t)(n*1152 + ks*32) + b_off;
                ldsm2(sb + GWH + bo + boW, bh0, bh1);
                ldsm2(sb + GWL + bo + boW, bl0, bl1);
                mma16816(c[n], ah, bh0, bh1);
                mma16816(c[n], ah, bl0, bl1);
                mma16816(c[n], al, bh0, bh1);
            }
        }
        __syncthreads();
    }

    // ---- epilogue: stage fp32 C tile in smem, then coalesced stores ----
    float* Csm = (float*)smp;                  // [128][68]
    const int r0l = w*16 + (lane >> 2), r1l = r0l + 8;
    const int cbase = 2*(lane & 3);
    #pragma unroll
    for (int n = 0; n < 8; n++) {
        *(float2*)&Csm[r0l*68 + n*8 + cbase] = make_float2(c[n][0], c[n][1]);
        *(float2*)&Csm[r1l*68 + n*8 + cbase] = make_float2(c[n][2], c[n][3]);
    }
    __syncthreads();

    if (scatter) {
        const int d0 = bn >> 3;
        #pragma unroll
        for (int k = 0; k < 4; k++) {
            int id = tid + k*256;              // 1024 chunks: (h, row)
            int hh = id & 7, row = id >> 3;
            uint32_t hi[4], lo[4];
            #pragma unroll
            for (int jj = 0; jj < 4; jj++) {
                float a = Csm[row*68 + (2*jj)*8 + hh];
                float b = Csm[row*68 + (2*jj + 1)*8 + hh];
                split2(a, b, hi[jj], lo[jj]);
            }
            int grow = bm + row, bb = grow >> 11, s = grow & 2047;
            size_t idx = (((size_t)bb*NH + hh)*SD + s)*DD + d0;
            *(uint4*)(oh + idx) = make_uint4(hi[0], hi[1], hi[2], hi[3]);
            *(uint4*)(ol + idx) = make_uint4(lo[0], lo[1], lo[2], lo[3]);
        }
    } else {
        #pragma unroll
        for (int k = 0; k < 8; k++) {
            int id = tid + k*256;              // 2048 quads
            int row = id >> 4, cq = (id & 15) * 4;
            float4 v = *(const float4*)&Csm[row*68 + cq];
            *(float4*)(out + (size_t)(bm + row)*ED + bn + cq) = v;
        }
    }
}

// ---------------------------------------------------------------------------
// cp.async double-buffered HMMA flash attention, full 3-term split-bf16:
//   S = QhKh + QhKl + QlKh      O += PhVh + PhVl + PlVh
// ids prefetched from gmem into registers (no smem staging).
// Per-half PV scheduling keeps P fragments transient (lower reg pressure).
// ---------------------------------------------------------------------------
#define AKH0 0                         // 2 bufs x 18432 each region
#define AKL0 36864
#define AVH0 73728
#define AVL0 110592
#define AQR  147456                    // f32 [128][37]
#define ARF  166400                    // f32 [34][68]
#define SMEM_ATT 175648
#define AQHT (AKH0 + 18432)            // prologue Q staging (buf1 of KH)
#define AQLT (AKL0 + 18432)            // prologue Q staging (buf1 of KL)

__device__ __forceinline__ void issue_tile(uint32_t sb, const char* Khg, const char* Klg,
                                           const char* Vhg, const char* Vlg,
                                           int k0, int buf, int tid)
{
    const uint32_t kv = (uint32_t)buf * 18432;
    for (int i = tid; i < 1024; i += 256) {
        int r = i >> 3;
        uint32_t cc = (uint32_t)(i & 7) * 16;
        uint32_t off = (uint32_t)r*144 + cc;
        size_t g = (size_t)(k0 + r)*128 + cc;
        cp16(sb + AKH0 + kv + off, Khg + g);
        cp16(sb + AKL0 + kv + off, Klg + g);
        cp16(sb + AVH0 + kv + off, Vhg + g);
        cp16(sb + AVL0 + kv + off, Vlg + g);
    }
}

__global__ __launch_bounds__(256, 1) void attn_mma(const float* __restrict__ rel_emb)
{
    extern __shared__ char smp[];
    const uint32_t sb = smem_u32(smp);
    const int tid = threadIdx.x, w = tid >> 5, lane = tid & 31;
    const int q0 = blockIdx.x * TQ, h = blockIdx.y, b = blockIdx.z;

    const size_t hb = ((size_t)(b*NH + h))*SD*DD;
    const char* Qhg = (const char*)(g_Qh + hb + (size_t)q0*DD);
    const char* Qlg = (const char*)(g_Ql + hb + (size_t)q0*DD);
    const char* Khg = (const char*)(g_Kh + hb);
    const char* Klg = (const char*)(g_Kl + hb);
    const char* Vhg = (const char*)(g_Vh + hb);
    const char* Vlg = (const char*)(g_Vl + hb);
    const unsigned char* idrow = g_rid8 + ((size_t)b*SD + q0)*SD;

    // ---- prologue: async-load Q split (into buf1 of KH/KL) + tile 0 ----
    for (int i = tid; i < 1024; i += 256) {
        int r = i >> 3;
        uint32_t cc = (uint32_t)(i & 7) * 16;
        uint32_t off = (uint32_t)r*144 + cc;
        size_t g = (size_t)r*128 + cc;
        cp16(sb + AQHT + off, Qhg + g);
        cp16(sb + AQLT + off, Qlg + g);
    }
    issue_tile(sb, Khg, Klg, Vhg, Vlg, 0, 0, tid);
    CP_COMMIT();
    float* Rf = (float*)(smp + ARF);
    for (int i = tid; i < PD*DD; i += 256) {
        int p = i >> 6, d = i & 63;
        Rf[p*68 + d] = rel_emb[(size_t)p*ED + d*NH + h];
    }
    CP_WAIT(0);
    __syncthreads();

    // Q fragments -> registers
    const int l8 = lane & 7, j = lane >> 3, l16 = lane & 15;
    const uint32_t a_off  = (uint32_t)((w*16 + ((j&1)<<3) + l8)*144 + ((j>>1)<<4));
    const uint32_t bs_off = (uint32_t)(l8*144 + ((l16>>3)<<4));
    const uint32_t bv_off = (uint32_t)(l16*144);
    uint32_t qh[4][4], ql[4][4];
    #pragma unroll
    for (int ks = 0; ks < 4; ks++) {
        ldsm4(sb + AQHT + a_off + ks*32, qh[ks]);
        ldsm4(sb + AQLT + a_off + ks*32, ql[ks]);
    }

    // Q_rel fp32 (hi+lo reconstruction)
    float* QR = (float*)(smp + AQR);
    for (int o = tid; o < TQ*PD; o += 256) {
        int q = o & 127, p = o >> 7;
        const float* rr = Rf + p*68;
        float s = 0.f;
        #pragma unroll 8
        for (int d = 0; d < 64; d += 2) {
            uint32_t h2 = *(const uint32_t*)(smp + AQHT + q*144 + d*2);
            uint32_t l2 = *(const uint32_t*)(smp + AQLT + q*144 + d*2);
            float2 hf2 = __bfloat1622float2(*(__nv_bfloat162*)&h2);
            float2 lf2 = __bfloat1622float2(*(__nv_bfloat162*)&l2);
            s = fmaf(hf2.x + lf2.x, rr[d],   s);
            s = fmaf(hf2.y + lf2.y, rr[d+1], s);
        }
        QR[q*37 + p] = s;
    }
    __syncthreads();   // Q frags + QR done; buf1 free for tile 1 prefetch

    float o_[8][4];
    #pragma unroll
    for (int n = 0; n < 8; n++) { o_[n][0]=0.f; o_[n][1]=0.f; o_[n][2]=0.f; o_[n][3]=0.f; }
    float rs0 = 0.f, rs1 = 0.f;
    const int r0 = w*16 + (lane >> 2), r1 = r0 + 8;
    const int cbase = 2*(lane & 3);

    for (int it = 0; it < NTILE; it++) {
        const int buf = it & 1;
        if (it + 1 < NTILE) {
            issue_tile(sb, Khg, Klg, Vhg, Vlg, (it+1)*TK, buf^1, tid);
            CP_COMMIT();
            CP_WAIT(1);
        } else {
            CP_WAIT(0);
        }
        __syncthreads();

        const uint32_t kv = (uint32_t)buf * 18432;
        const int k0 = it * TK;

        // prefetch ids for this tile (scattered u8 loads, L2-resident)
        uchar2 idA[16], idB[16];
        #pragma unroll
        for (int ng = 0; ng < 16; ng++) {
            int cc = ng*8 + cbase;
            idA[ng] = *(const uchar2*)(idrow + (size_t)r0*SD + k0 + cc);
            idB[ng] = *(const uchar2*)(idrow + (size_t)r1*SD + k0 + cc);
        }

        #pragma unroll
        for (int hf = 0; hf < 2; hf++) {
            // S half: 128q x 64k, 3 terms
            float c[8][4];
            #pragma unroll
            for (int n = 0; n < 8; n++) { c[n][0]=0.f; c[n][1]=0.f; c[n][2]=0.f; c[n][3]=0.f; }
            #pragma unroll
            for (int ks = 0; ks < 4; ks++) {
                #pragma unroll
                for (int n = 0; n < 8; n++) {
                    uint32_t bh0, bh1, bl0, bl1;
                    uint32_t bo = (uint32_t)((hf*8 + n)*1152 + ks*32) + bs_off;
                    ldsm2(sb + AKH0 + kv + bo, bh0, bh1);
                    ldsm2(sb + AKL0 + kv + bo, bl0, bl1);
                    mma16816(c[n], qh[ks], bh0, bh1);
                    mma16816(c[n], qh[ks], bl0, bl1);
                    mma16816(c[n], ql[ks], bh0, bh1);
                }
            }
            // softmax + split-bf16 repack into PV A-frags (register-resident P)
            uint32_t ph[4][4], pl[4][4];
            #pragma unroll
            for (int n = 0; n < 8; n++) {
                int ng = hf*8 + n;
                uchar2 i0 = idA[ng], i1 = idB[ng];
                float p0 = i0.x ? __expf((c[n][0] + QR[r0*37 + i0.x]) * 0.125f) : 0.f;
                float p1 = i0.y ? __expf((c[n][1] + QR[r0*37 + i0.y]) * 0.125f) : 0.f;
                float p2 = i1.x ? __expf((c[n][2] + QR[r1*37 + i1.x]) * 0.125f) : 0.f;
                float p3 = i1.y ? __expf((c[n][3] + QR[r1*37 + i1.y]) * 0.125f) : 0.f;
                rs0 += p0 + p1; rs1 += p2 + p3;
                uint32_t hA, lA, hB, lB;
                split2(p0, p1, hA, lA);
                split2(p2, p3, hB, lB);
                int kl = n >> 1, oo = (n & 1) * 2;
                ph[kl][oo] = hA; ph[kl][oo+1] = hB;
                pl[kl][oo] = lA; pl[kl][oo+1] = lB;
            }
            // O += PhVh + PhVl + PlVh (this half's 64 keys)
            #pragma unroll
            for (int kl = 0; kl < 4; kl++) {
                int ks = hf*4 + kl;
                #pragma unroll
                for (int n = 0; n < 8; n++) {
                    uint32_t bh0, bh1, bl0, bl1;
                    uint32_t bo = (uint32_t)(ks*2304 + n*16) + bv_off;
                    ldsm2t(sb + AVH0 + kv + bo, bh0, bh1);
                    ldsm2t(sb + AVL0 + kv + bo, bl0, bl1);
                    mma16816(o_[n], ph[kl], bh0, bh1);
                    mma16816(o_[n], ph[kl], bl0, bl1);
                    mma16816(o_[n], pl[kl], bh0, bh1);
                }
            }
        }
        __syncthreads();   // retire reads of buf before it is refilled
    }

    // ---- epilogue ----
    rs0 += __shfl_xor_sync(0xffffffffu, rs0, 1);
    rs0 += __shfl_xor_sync(0xffffffffu, rs0, 2);
    rs1 += __shfl_xor_sync(0xffffffffu, rs1, 1);
    rs1 += __shfl_xor_sync(0xffffffffu, rs1, 2);
    const float i0 = 1.f / rs0, i1 = 1.f / rs1;

    float* ob0 = g_AttO + ((size_t)(b*SD + q0 + r0))*ED + h;
    float* ob1 = g_AttO + ((size_t)(b*SD + q0 + r1))*ED + h;
    #pragma unroll
    for (int n = 0; n < 8; n++) {
        int d = n*8 + cbase;
        ob0[(d+0)*NH] = o_[n][0] * i0;
        ob0[(d+1)*NH] = o_[n][1] * i0;
        ob1[(d+0)*NH] = o_[n][2] * i1;
        ob1[(d+1)*NH] = o_[n][3] * i1;
    }
}

// ---------------------------------------------------------------------------
extern "C" void kernel_launch(void* const* d_in, const int* in_sizes, int n_in,
                              void* d_out, int out_size)
{
    const float* Q   = (const float*)d_in[0];
    const float* K   = (const float*)d_in[1];
    const float* V   = (const float*)d_in[2];
    const int*   rid = (const int*)d_in[3];
    const float* Wq  = (const float*)d_in[4];
    const float* Wk  = (const float*)d_in[5];
    const float* Wv  = (const float*)d_in[6];
    const float* Wo  = (const float*)d_in[7];
    const float* re  = (const float*)d_in[8];
    float* out = (float*)d_out;

    __nv_bfloat16 *Qh, *Ql, *Kh, *Kl, *Vh, *Vl, *Xh, *Xl, *Wh, *Wl;
    float* AttO;
    unsigned char* rid8;
    cudaGetSymbolAddress((void**)&Qh, g_Qh);
    cudaGetSymbolAddress((void**)&Ql, g_Ql);
    cudaGetSymbolAddress((void**)&Kh, g_Kh);
    cudaGetSymbolAddress((void**)&Kl, g_Kl);
    cudaGetSymbolAddress((void**)&Vh, g_Vh);
    cudaGetSymbolAddress((void**)&Vl, g_Vl);
    cudaGetSymbolAddress((void**)&Xh, g_Xh);
    cudaGetSymbolAddress((void**)&Xl, g_Xl);
    cudaGetSymbolAddress((void**)&Wh, g_Wh);
    cudaGetSymbolAddress((void**)&Wl, g_Wl);
    cudaGetSymbolAddress((void**)&AttO, g_AttO);
    cudaGetSymbolAddress((void**)&rid8, g_rid8);

    cudaFuncSetAttribute((const void*)attn_mma,
                         cudaFuncAttributeMaxDynamicSharedMemorySize, SMEM_ATT);
    cudaFuncSetAttribute((const void*)gemm_mma,
                         cudaFuncAttributeMaxDynamicSharedMemorySize, GSMEM);

    dim3 t(256);
    rid_pack<<<(BD*SD*SD)/(256*16), t>>>(rid, rid8);

    dim3 g1(32, 8);
    const int NX = BD*SD*ED/1024;
    const int NW = ED*ED/1024;

    to_split<<<NX, t>>>(Q,  Xh, Xl);
    to_split<<<NW, t>>>(Wq, Wh, Wl);
    gemm_mma<<<g1, t, GSMEM>>>(Xh, Xl, Wh, Wl, nullptr, Qh, Ql, 1);

    to_split<<<NX, t>>>(K,  Xh, Xl);
    to_split<<<NW, t>>>(Wk, Wh, Wl);
    gemm_mma<<<g1, t, GSMEM>>>(Xh, Xl, Wh, Wl, nullptr, Kh, Kl, 1);

    to_split<<<NX, t>>>(V,  Xh, Xl);
    to_split<<<NW, t>>>(Wv, Wh, Wl);
    gemm_mma<<<g1, t, GSMEM>>>(Xh, Xl, Wh, Wl, nullptr, Vh, Vl, 1);

    dim3 g2(SD/TQ, NH, BD);            // (16, 8, 2)
    attn_mma<<<g2, t, SMEM_ATT>>>(re);

    to_split<<<NX, t>>>(AttO, Xh, Xl);
    to_split<<<NW, t>>>(Wo,   Wh, Wl);
    gemm_mma<<<g1, t, GSMEM>>>(Xh, Xl, Wh, Wl, out, nullptr, nullptr, 0);
}

// round 16
// speedup vs baseline: 1.1357x; 1.1357x over previous
#include <cuda_runtime.h>
#include <cuda_bf16.h>
#include <cstdint>

#define BD 2
#define SD 2048
#define ED 512
#define NH 8     // heads
#define DD 64    // head dim
#define PD 34    // num pos ids
#define TQ 128   // queries per CTA
#define TK 128   // keys per tile
#define NTILE (SD/TK)

// scratch (allocation-free)
__device__ __nv_bfloat16 g_Qh[BD*NH*SD*DD];
__device__ __nv_bfloat16 g_Ql[BD*NH*SD*DD];
__device__ __nv_bfloat16 g_Kh[BD*NH*SD*DD];
__device__ __nv_bfloat16 g_Kl[BD*NH*SD*DD];
__device__ __nv_bfloat16 g_Vh[BD*NH*SD*DD];
__device__ __nv_bfloat16 g_Vl[BD*NH*SD*DD];
__device__ float g_AttO[BD*SD*ED];
__device__ unsigned char g_rid8[BD*SD*SD];
__device__ __nv_bfloat16 g_Xh[BD*SD*ED];      // pre-split gemm input
__device__ __nv_bfloat16 g_Xl[BD*SD*ED];
__device__ __nv_bfloat16 g_Wh[ED*ED];         // pre-split gemm weight
__device__ __nv_bfloat16 g_Wl[ED*ED];

// ---------------------------------------------------------------------------
// common helpers
// ---------------------------------------------------------------------------
__device__ __forceinline__ uint32_t smem_u32(const void* p) {
    uint32_t a;
    asm("{ .reg .u64 t; cvta.to.shared.u64 t, %1; cvt.u32.u64 %0, t; }"
        : "=r"(a) : "l"(p));
    return a;
}
__device__ __forceinline__ void ldsm4(uint32_t addr, uint32_t* r) {
    asm volatile("ldmatrix.sync.aligned.m8n8.x4.shared.b16 {%0,%1,%2,%3}, [%4];"
                 : "=r"(r[0]), "=r"(r[1]), "=r"(r[2]), "=r"(r[3]) : "r"(addr));
}
__device__ __forceinline__ void ldsm2(uint32_t addr, uint32_t& r0, uint32_t& r1) {
    asm volatile("ldmatrix.sync.aligned.m8n8.x2.shared.b16 {%0,%1}, [%2];"
                 : "=r"(r0), "=r"(r1) : "r"(addr));
}
__device__ __forceinline__ void ldsm2t(uint32_t addr, uint32_t& r0, uint32_t& r1) {
    asm volatile("ldmatrix.sync.aligned.m8n8.x2.trans.shared.b16 {%0,%1}, [%2];"
                 : "=r"(r0), "=r"(r1) : "r"(addr));
}
__device__ __forceinline__ void mma16816(float* c, const uint32_t* a,
                                         uint32_t b0, uint32_t b1) {
    asm volatile("mma.sync.aligned.m16n8k16.row.col.f32.bf16.bf16.f32 "
                 "{%0,%1,%2,%3}, {%4,%5,%6,%7}, {%8,%9}, {%0,%1,%2,%3};"
                 : "+f"(c[0]), "+f"(c[1]), "+f"(c[2]), "+f"(c[3])
                 : "r"(a[0]), "r"(a[1]), "r"(a[2]), "r"(a[3]), "r"(b0), "r"(b1));
}
__device__ __forceinline__ uint32_t pack2(__nv_bfloat16 a, __nv_bfloat16 b) {
    return (uint32_t)__bfloat16_as_ushort(a) | ((uint32_t)__bfloat16_as_ushort(b) << 16);
}
__device__ __forceinline__ void split2(float x0, float x1, uint32_t& hi, uint32_t& lo) {
    __nv_bfloat16 h0 = __float2bfloat16(x0), h1 = __float2bfloat16(x1);
    hi = pack2(h0, h1);
    lo = pack2(__float2bfloat16(x0 - __bfloat162float(h0)),
               __float2bfloat16(x1 - __bfloat162float(h1)));
}
__device__ __forceinline__ void cp16(uint32_t dst, const void* src) {
    asm volatile("cp.async.cg.shared.global [%0], [%1], 16;" :: "r"(dst), "l"(src));
}
#define CP_COMMIT() asm volatile("cp.async.commit_group;" ::: "memory")
#define CP_WAIT(n)  asm volatile("cp.async.wait_group %0;" :: "n"(n) : "memory")

// ---------------------------------------------------------------------------
// rid int32 -> u8 pack (once)
// ---------------------------------------------------------------------------
__global__ __launch_bounds__(256) void rid_pack(const int* __restrict__ rid,
                                                unsigned char* __restrict__ out)
{
    size_t i = (size_t)blockIdx.x * 256 + threadIdx.x;   // 16 elems per thread
    const int4* src = (const int4*)rid + i * 4;
    int4 a = src[0], b = src[1], c = src[2], d = src[3];
    uint4 r;
    r.x = (uint32_t)a.x | ((uint32_t)a.y << 8) | ((uint32_t)a.z << 16) | ((uint32_t)a.w << 24);
    r.y = (uint32_t)b.x | ((uint32_t)b.y << 8) | ((uint32_t)b.z << 16) | ((uint32_t)b.w << 24);
    r.z = (uint32_t)c.x | ((uint32_t)c.y << 8) | ((uint32_t)c.z << 16) | ((uint32_t)c.w << 24);
    r.w = (uint32_t)d.x | ((uint32_t)d.y << 8) | ((uint32_t)d.z << 16) | ((uint32_t)d.w << 24);
    *(uint4*)(out + i * 16) = r;
}

// ---------------------------------------------------------------------------
// fp32 -> split bf16 (hi, lo), row-major preserved
// ---------------------------------------------------------------------------
__global__ __launch_bounds__(256) void to_split(const float* __restrict__ in,
                                                __nv_bfloat16* __restrict__ oh,
                                                __nv_bfloat16* __restrict__ ol)
{
    size_t i = ((size_t)blockIdx.x * 256 + threadIdx.x) * 4;
    float4 v = *(const float4*)(in + i);
    uint32_t h0, l0, h1, l1;
    split2(v.x, v.y, h0, l0);
    split2(v.z, v.w, h1, l1);
    *(uint2*)(oh + i) = make_uint2(h0, h1);
    *(uint2*)(ol + i) = make_uint2(l0, l1);
}

// ---------------------------------------------------------------------------
// HMMA split-bf16 GEMM (pre-split operands, cp.async double buffer)
// ---------------------------------------------------------------------------
#define GXH  0
#define GXL  18432
#define GWH  36864
#define GWL  46080
#define GBUF 55296
#define GSMEM 110592

__device__ __forceinline__ void gemm_issue(uint32_t sb, int buf, int kt,
                                           int bm, int bn, int tid,
                                           const char* Xh, const char* Xl,
                                           const char* Wh, const char* Wl)
{
    const uint32_t bo = (uint32_t)buf * GBUF;
    const int k0b = kt * 128;
    for (int i = tid; i < 1024; i += 256) {
        int r = i >> 3;
        uint32_t cc = (uint32_t)(i & 7) * 16;
        uint32_t off = (uint32_t)r * 144 + cc;
        size_t g = (size_t)(bm + r) * 1024 + k0b + cc;
        cp16(sb + GXH + bo + off, Xh + g);
        cp16(sb + GXL + bo + off, Xl + g);
    }
    for (int i = tid; i < 512; i += 256) {
        int r = i >> 3;
        uint32_t cc = (uint32_t)(i & 7) * 16;
        uint32_t off = (uint32_t)r * 144 + cc;
        size_t g = (size_t)(bn + r) * 1024 + k0b + cc;
        cp16(sb + GWH + bo + off, Wh + g);
        cp16(sb + GWL + bo + off, Wl + g);
    }
}

__global__ __launch_bounds__(256, 2) void gemm_mma(const __nv_bfloat16* __restrict__ Xh_,
                                                   const __nv_bfloat16* __restrict__ Xl_,
                                                   const __nv_bfloat16* __restrict__ Wh_,
                                                   const __nv_bfloat16* __restrict__ Wl_,
                                                   float* __restrict__ out,
                                                   __nv_bfloat16* __restrict__ oh,
                                                   __nv_bfloat16* __restrict__ ol,
                                                   int scatter)
{
    extern __shared__ char smp[];
    const uint32_t sb = smem_u32(smp);
    const int tid = threadIdx.x, w = tid >> 5, lane = tid & 31;
    const int bm = blockIdx.x * 128, bn = blockIdx.y * 64;
    const char* Xh = (const char*)Xh_;
    const char* Xl = (const char*)Xl_;
    const char* Wh = (const char*)Wh_;
    const char* Wl = (const char*)Wl_;
    const int l8 = lane & 7, j = lane >> 3, l16 = lane & 15;
    const uint32_t a_off = (uint32_t)((w*16 + ((j&1)<<3) + l8)*144 + ((j>>1)<<4));
    const uint32_t b_off = (uint32_t)(l8*144 + ((l16>>3)<<4));

    float c[8][4];
    #pragma unroll
    for (int n = 0; n < 8; n++) { c[n][0]=0.f; c[n][1]=0.f; c[n][2]=0.f; c[n][3]=0.f; }

    gemm_issue(sb, 0, 0, bm, bn, tid, Xh, Xl, Wh, Wl);
    CP_COMMIT();

    for (int kt = 0; kt < 8; kt++) {
        const int buf = kt & 1;
        if (kt + 1 < 8) {
            gemm_issue(sb, buf ^ 1, kt + 1, bm, bn, tid, Xh, Xl, Wh, Wl);
            CP_COMMIT();
            CP_WAIT(1);
        } else {
            CP_WAIT(0);
        }
        __syncthreads();
        const uint32_t bo = (uint32_t)buf * GBUF;

        #pragma unroll
        for (int ks = 0; ks < 4; ks++) {
            uint32_t ah[4], al[4];
            ldsm4(sb + GXH + bo + a_off + ks*32, ah);
            ldsm4(sb + GXL + bo + a_off + ks*32, al);
            #pragma unroll
            for (int n = 0; n < 8; n++) {
                uint32_t bh0, bh1, bl0, bl1;
                uint32_t boW = (uint32_t)(n*1152 + ks*32) + b_off;
                ldsm2(sb + GWH + bo + boW, bh0, bh1);
                ldsm2(sb + GWL + bo + boW, bl0, bl1);
                mma16816(c[n], ah, bh0, bh1);
                mma16816(c[n], ah, bl0, bl1);
                mma16816(c[n], al, bh0, bh1);
            }
        }
        __syncthreads();
    }

    // ---- epilogue: stage fp32 C tile in smem, then coalesced stores ----
    float* Csm = (float*)smp;                  // [128][68]
    const int r0l = w*16 + (lane >> 2), r1l = r0l + 8;
    const int cbase = 2*(lane & 3);
    #pragma unroll
    for (int n = 0; n < 8; n++) {
        *(float2*)&Csm[r0l*68 + n*8 + cbase] = make_float2(c[n][0], c[n][1]);
        *(float2*)&Csm[r1l*68 + n*8 + cbase] = make_float2(c[n][2], c[n][3]);
    }
    __syncthreads();

    if (scatter) {
        const int d0 = bn >> 3;
        #pragma unroll
        for (int k = 0; k < 4; k++) {
            int id = tid + k*256;              // 1024 chunks: (h, row)
            int hh = id & 7, row = id >> 3;
            uint32_t hi[4], lo[4];
            #pragma unroll
            for (int jj = 0; jj < 4; jj++) {
                float a = Csm[row*68 + (2*jj)*8 + hh];
                float b = Csm[row*68 + (2*jj + 1)*8 + hh];
                split2(a, b, hi[jj], lo[jj]);
            }
            int grow = bm + row, bb = grow >> 11, s = grow & 2047;
            size_t idx = (((size_t)bb*NH + hh)*SD + s)*DD + d0;
            *(uint4*)(oh + idx) = make_uint4(hi[0], hi[1], hi[2], hi[3]);
            *(uint4*)(ol + idx) = make_uint4(lo[0], lo[1], lo[2], lo[3]);
        }
    } else {
        #pragma unroll
        for (int k = 0; k < 8; k++) {
            int id = tid + k*256;              // 2048 quads
            int row = id >> 4, cq = (id & 15) * 4;
            float4 v = *(const float4*)&Csm[row*68 + cq];
            *(float4*)(out + (size_t)(bm + row)*ED + bn + cq) = v;
        }
    }
}

// ---------------------------------------------------------------------------
// 512-thread cp.async double-buffered HMMA flash attention.
// 16 warps: warp (qw, half) owns q rows [qw*16, qw*16+16) x key-half `half`
// of each 128-key tile. Per n-pair S -> softmax -> PV keeps fragments
// transient (regs < 128). Partner halves reduce O + rowsum via smem.
// Full 3-term split-bf16: S = QhKh+QhKl+QlKh ; O += PhVh+PhVl+PlVh.
// ---------------------------------------------------------------------------
#define AKH0 0                         // 2 bufs x 18432 each region
#define AKL0 36864
#define AVH0 73728
#define AVL0 110592
#define AQR  147456                    // f32 [128][37]
#define ARF  166400                    // f32 [34][68]
#define SMEM_ATT 175648
#define AQHT (AKH0 + 18432)            // prologue Q staging (buf1 of KH)
#define AQLT (AKL0 + 18432)            // prologue Q staging (buf1 of KL)

__device__ __forceinline__ void issue_tile(uint32_t sb, const char* Khg, const char* Klg,
                                           const char* Vhg, const char* Vlg,
                                           int k0, int buf, int tid)
{
    const uint32_t kv = (uint32_t)buf * 18432;
    for (int i = tid; i < 1024; i += 512) {
        int r = i >> 3;
        uint32_t cc = (uint32_t)(i & 7) * 16;
        uint32_t off = (uint32_t)r*144 + cc;
        size_t g = (size_t)(k0 + r)*128 + cc;
        cp16(sb + AKH0 + kv + off, Khg + g);
        cp16(sb + AKL0 + kv + off, Klg + g);
        cp16(sb + AVH0 + kv + off, Vhg + g);
        cp16(sb + AVL0 + kv + off, Vlg + g);
    }
}

__global__ __launch_bounds__(512, 1) void attn_mma(const float* __restrict__ rel_emb)
{
    extern __shared__ char smp[];
    const uint32_t sb = smem_u32(smp);
    const int tid = threadIdx.x, w = tid >> 5, lane = tid & 31;
    const int qw = w >> 1, half = w & 1;
    const int q0 = blockIdx.x * TQ, h = blockIdx.y, b = blockIdx.z;

    const size_t hb = ((size_t)(b*NH + h))*SD*DD;
    const char* Qhg = (const char*)(g_Qh + hb + (size_t)q0*DD);
    const char* Qlg = (const char*)(g_Ql + hb + (size_t)q0*DD);
    const char* Khg = (const char*)(g_Kh + hb);
    const char* Klg = (const char*)(g_Kl + hb);
    const char* Vhg = (const char*)(g_Vh + hb);
    const char* Vlg = (const char*)(g_Vl + hb);
    const unsigned char* idrow = g_rid8 + ((size_t)b*SD + q0)*SD;

    // ---- prologue: async-load Q split (into buf1 of KH/KL) + tile 0 ----
    for (int i = tid; i < 1024; i += 512) {
        int r = i >> 3;
        uint32_t cc = (uint32_t)(i & 7) * 16;
        uint32_t off = (uint32_t)r*144 + cc;
        size_t g = (size_t)r*128 + cc;
        cp16(sb + AQHT + off, Qhg + g);
        cp16(sb + AQLT + off, Qlg + g);
    }
    issue_tile(sb, Khg, Klg, Vhg, Vlg, 0, 0, tid);
    CP_COMMIT();
    float* Rf = (float*)(smp + ARF);
    for (int i = tid; i < PD*DD; i += 512) {
        int p = i >> 6, d = i & 63;
        Rf[p*68 + d] = rel_emb[(size_t)p*ED + d*NH + h];
    }
    CP_WAIT(0);
    __syncthreads();

    // Q fragments -> registers (warp's 16 q rows)
    const int l8 = lane & 7, j = lane >> 3, l16 = lane & 15;
    const uint32_t a_off  = (uint32_t)((qw*16 + ((j&1)<<3) + l8)*144 + ((j>>1)<<4));
    const uint32_t bs_off = (uint32_t)(l8*144 + ((l16>>3)<<4));
    const uint32_t bv_off = (uint32_t)(l16*144);
    uint32_t qh[4][4], ql[4][4];
    #pragma unroll
    for (int ks = 0; ks < 4; ks++) {
        ldsm4(sb + AQHT + a_off + ks*32, qh[ks]);
        ldsm4(sb + AQLT + a_off + ks*32, ql[ks]);
    }

    // Q_rel fp32 (hi+lo reconstruction)
    float* QR = (float*)(smp + AQR);
    for (int o = tid; o < TQ*PD; o += 512) {
        int q = o & 127, p = o >> 7;
        const float* rr = Rf + p*68;
        float s = 0.f;
        #pragma unroll 8
        for (int d = 0; d < 64; d += 2) {
            uint32_t h2 = *(const uint32_t*)(smp + AQHT + q*144 + d*2);
            uint32_t l2 = *(const uint32_t*)(smp + AQLT + q*144 + d*2);
            float2 hf2 = __bfloat1622float2(*(__nv_bfloat162*)&h2);
            float2 lf2 = __bfloat1622float2(*(__nv_bfloat162*)&l2);
            s = fmaf(hf2.x + lf2.x, rr[d],   s);
            s = fmaf(hf2.y + lf2.y, rr[d+1], s);
        }
        QR[q*37 + p] = s;
    }
    __syncthreads();   // Q frags + QR done; buf1 free for tile 1 prefetch

    float o_[8][4];
    #pragma unroll
    for (int d = 0; d < 8; d++) { o_[d][0]=0.f; o_[d][1]=0.f; o_[d][2]=0.f; o_[d][3]=0.f; }
    float rs0 = 0.f, rs1 = 0.f;
    const int r0 = qw*16 + (lane >> 2), r1 = r0 + 8;
    const int cbase = 2*(lane & 3);
    const int kbase = half * 64;

    for (int it = 0; it < NTILE; it++) {
        const int buf = it & 1;
        if (it + 1 < NTILE) {
            issue_tile(sb, Khg, Klg, Vhg, Vlg, (it+1)*TK, buf^1, tid);
            CP_COMMIT();
            CP_WAIT(1);
        } else {
            CP_WAIT(0);
        }
        __syncthreads();

        const uint32_t kv = (uint32_t)buf * 18432;
        const int k0 = it * TK;

        // prefetch ids for this warp's key-half (L2-resident)
        uchar2 idA[8], idB[8];
        #pragma unroll
        for (int ng = 0; ng < 8; ng++) {
            int cc = kbase + ng*8 + cbase;
            idA[ng] = *(const uchar2*)(idrow + (size_t)r0*SD + k0 + cc);
            idB[ng] = *(const uchar2*)(idrow + (size_t)r1*SD + k0 + cc);
        }

        #pragma unroll
        for (int pair = 0; pair < 4; pair++) {
            // S for 2 n-blocks (16 keys), 3 split terms
            float c0[4] = {0.f,0.f,0.f,0.f}, c1[4] = {0.f,0.f,0.f,0.f};
            #pragma unroll
            for (int ks = 0; ks < 4; ks++) {
                uint32_t bh0, bh1, bl0, bl1;
                uint32_t bo0 = (uint32_t)((half*8 + pair*2)*1152 + ks*32) + bs_off;
                ldsm2(sb + AKH0 + kv + bo0, bh0, bh1);
                ldsm2(sb + AKL0 + kv + bo0, bl0, bl1);
                mma16816(c0, qh[ks], bh0, bh1);
                mma16816(c0, qh[ks], bl0, bl1);
                mma16816(c0, ql[ks], bh0, bh1);
                uint32_t bo1 = bo0 + 1152;
                ldsm2(sb + AKH0 + kv + bo1, bh0, bh1);
                ldsm2(sb + AKL0 + kv + bo1, bl0, bl1);
                mma16816(c1, qh[ks], bh0, bh1);
                mma16816(c1, qh[ks], bl0, bl1);
                mma16816(c1, ql[ks], bh0, bh1);
            }
            // softmax (no online max: |logit| small by construction)
            uchar2 iA0 = idA[pair*2],   iB0 = idB[pair*2];
            uchar2 iA1 = idA[pair*2+1], iB1 = idB[pair*2+1];
            float p0 = iA0.x ? __expf((c0[0] + QR[r0*37 + iA0.x]) * 0.125f) : 0.f;
            float p1 = iA0.y ? __expf((c0[1] + QR[r0*37 + iA0.y]) * 0.125f) : 0.f;
            float p2 = iB0.x ? __expf((c0[2] + QR[r1*37 + iB0.x]) * 0.125f) : 0.f;
            float p3 = iB0.y ? __expf((c0[3] + QR[r1*37 + iB0.y]) * 0.125f) : 0.f;
            float p4 = iA1.x ? __expf((c1[0] + QR[r0*37 + iA1.x]) * 0.125f) : 0.f;
            float p5 = iA1.y ? __expf((c1[1] + QR[r0*37 + iA1.y]) * 0.125f) : 0.f;
            float p6 = iB1.x ? __expf((c1[2] + QR[r1*37 + iB1.x]) * 0.125f) : 0.f;
            float p7 = iB1.y ? __expf((c1[3] + QR[r1*37 + iB1.y]) * 0.125f) : 0.f;
            rs0 += p0 + p1 + p4 + p5;
            rs1 += p2 + p3 + p6 + p7;
            uint32_t ph[4], pl[4];
            split2(p0, p1, ph[0], pl[0]);
            split2(p2, p3, ph[1], pl[1]);
            split2(p4, p5, ph[2], pl[2]);
            split2(p6, p7, ph[3], pl[3]);
            // PV for these 16 keys over all 8 d-blocks
            const int ksv = half*4 + pair;
            #pragma unroll
            for (int d = 0; d < 8; d++) {
                uint32_t bh0, bh1, bl0, bl1;
                uint32_t bo = (uint32_t)(ksv*2304 + d*16) + bv_off;
                ldsm2t(sb + AVH0 + kv + bo, bh0, bh1);
                ldsm2t(sb + AVL0 + kv + bo, bl0, bl1);
                mma16816(o_[d], ph, bh0, bh1);
                mma16816(o_[d], ph, bl0, bl1);
                mma16816(o_[d], pl, bh0, bh1);
            }
        }
        __syncthreads();   // retire reads of buf before it is refilled
    }

    // ---- epilogue: reduce partner halves via smem, normalize, store ----
    rs0 += __shfl_xor_sync(0xffffffffu, rs0, 1);
    rs0 += __shfl_xor_sync(0xffffffffu, rs0, 2);
    rs1 += __shfl_xor_sync(0xffffffffu, rs1, 1);
    rs1 += __shfl_xor_sync(0xffffffffu, rs1, 2);

    float* Osm = (float*)smp;                   // [128][68] (KH region)
    float* Rsm = (float*)(smp + AVH0);          // [128]
    if (half == 0) {
        #pragma unroll
        for (int d = 0; d < 8; d++) {
            *(float2*)&Osm[r0*68 + d*8 + cbase] = make_float2(o_[d][0], o_[d][1]);
            *(float2*)&Osm[r1*68 + d*8 + cbase] = make_float2(o_[d][2], o_[d][3]);
        }
        if ((lane & 3) == 0) { Rsm[r0] = rs0; Rsm[r1] = rs1; }
    }
    __syncthreads();
    if (half == 1) {
        #pragma unroll
        for (int d = 0; d < 8; d++) {
            float2 t0 = *(float2*)&Osm[r0*68 + d*8 + cbase];
            float2 t1 = *(float2*)&Osm[r1*68 + d*8 + cbase];
            *(float2*)&Osm[r0*68 + d*8 + cbase] = make_float2(t0.x + o_[d][0], t0.y + o_[d][1]);
            *(float2*)&Osm[r1*68 + d*8 + cbase] = make_float2(t1.x + o_[d][2], t1.y + o_[d][3]);
        }
        if ((lane & 3) == 0) { Rsm[r0] += rs0; Rsm[r1] += rs1; }
    }
    __syncthreads();

    for (int i = tid; i < TQ*DD; i += 512) {
        int row = i >> 6, d = i & 63;
        float inv = 1.f / Rsm[row];
        g_AttO[((size_t)(b*SD + q0 + row))*ED + d*NH + h] = Osm[row*68 + d] * inv;
    }
}

// ---------------------------------------------------------------------------
extern "C" void kernel_launch(void* const* d_in, const int* in_sizes, int n_in,
                              void* d_out, int out_size)
{
    const float* Q   = (const float*)d_in[0];
    const float* K   = (const float*)d_in[1];
    const float* V   = (const float*)d_in[2];
    const int*   rid = (const int*)d_in[3];
    const float* Wq  = (const float*)d_in[4];
    const float* Wk  = (const float*)d_in[5];
    const float* Wv  = (const float*)d_in[6];
    const float* Wo  = (const float*)d_in[7];
    const float* re  = (const float*)d_in[8];
    float* out = (float*)d_out;

    __nv_bfloat16 *Qh, *Ql, *Kh, *Kl, *Vh, *Vl, *Xh, *Xl, *Wh, *Wl;
    float* AttO;
    unsigned char* rid8;
    cudaGetSymbolAddress((void**)&Qh, g_Qh);
    cudaGetSymbolAddress((void**)&Ql, g_Ql);
    cudaGetSymbolAddress((void**)&Kh, g_Kh);
    cudaGetSymbolAddress((void**)&Kl, g_Kl);
    cudaGetSymbolAddress((void**)&Vh, g_Vh);
    cudaGetSymbolAddress((void**)&Vl, g_Vl);
    cudaGetSymbolAddress((void**)&Xh, g_Xh);
    cudaGetSymbolAddress((void**)&Xl, g_Xl);
    cudaGetSymbolAddress((void**)&Wh, g_Wh);
    cudaGetSymbolAddress((void**)&Wl, g_Wl);
    cudaGetSymbolAddress((void**)&AttO, g_AttO);
    cudaGetSymbolAddress((void**)&rid8, g_rid8);

    cudaFuncSetAttribute((const void*)attn_mma,
                         cudaFuncAttributeMaxDynamicSharedMemorySize, SMEM_ATT);
    cudaFuncSetAttribute((const void*)gemm_mma,
                         cudaFuncAttributeMaxDynamicSharedMemorySize, GSMEM);

    dim3 t(256);
    rid_pack<<<(BD*SD*SD)/(256*16), t>>>(rid, rid8);

    dim3 g1(32, 8);
    const int NX = BD*SD*ED/1024;
    const int NW = ED*ED/1024;

    to_split<<<NX, t>>>(Q,  Xh, Xl);
    to_split<<<NW, t>>>(Wq, Wh, Wl);
    gemm_mma<<<g1, t, GSMEM>>>(Xh, Xl, Wh, Wl, nullptr, Qh, Ql, 1);

    to_split<<<NX, t>>>(K,  Xh, Xl);
    to_split<<<NW, t>>>(Wk, Wh, Wl);
    gemm_mma<<<g1, t, GSMEM>>>(Xh, Xl, Wh, Wl, nullptr, Kh, Kl, 1);

    to_split<<<NX, t>>>(V,  Xh, Xl);
    to_split<<<NW, t>>>(Wv, Wh, Wl);
    gemm_mma<<<g1, t, GSMEM>>>(Xh, Xl, Wh, Wl, nullptr, Vh, Vl, 1);

    dim3 g2(SD/TQ, NH, BD);            // (16, 8, 2)
    attn_mma<<<g2, dim3(512), SMEM_ATT>>>(re);

    to_split<<<NX, t>>>(AttO, Xh, Xl);
    to_split<<<NW, t>>>(Wo,   Wh, Wl);
    gemm_mma<<<g1, t, GSMEM>>>(Xh, Xl, Wh, Wl, out, nullptr, nullptr, 0);
}